// round 13
// baseline (speedup 1.0000x reference)
#include <cuda_runtime.h>
#include <cuda_fp16.h>
#include <math.h>
#include <stdint.h>

// ---------------- problem constants ----------------
#define B_WIN   2048
#define NTOK    49
#define DIM     384
#define NH      12
#define HD      32
#define NWMASK  64
#define TBL     169
#define CPBH    512
#define QKV_N   1152
#define MROWS   (B_WIN * NTOK)    // 100352
#define NN      (NTOK * NTOK)     // 2401
#define KDIM    384

// ---------------- scratch (device globals) ----------------
__device__ float  g_qkv[(size_t)MROWS * QKV_N];
__device__ __half g_xh[(size_t)MROWS * KDIM];
__device__ __half g_atth[(size_t)MROWS * DIM];
__device__ __half g_wh[(size_t)QKV_N * KDIM];
__device__ __half g_pwh[(size_t)DIM * KDIM];
__device__ float  g_bias_table[TBL * NH];
__device__ float  g_qkv_bias[QKV_N];
// bias+mask in mma C-fragment layout: [w][h][mi(4)][t(7)][lane(32)][4]
#define BMF_PER_WH (4 * 7 * 128)
__device__ float  g_bmF[(size_t)NWMASK * NH * BMF_PER_WH];

// ---------------- helpers ----------------
__device__ __forceinline__ uint32_t smem_u32(const void* p) {
    uint32_t a;
    asm("{ .reg .u64 t; cvta.to.shared.u64 t, %1; cvt.u32.u64 %0, t; }" : "=r"(a) : "l"(p));
    return a;
}
__device__ __forceinline__ void cp16(uint32_t dst, const void* src) {
    asm volatile("cp.async.ca.shared.global [%0], [%1], 16;" :: "r"(dst), "l"(src));
}
#define CP_COMMIT() asm volatile("cp.async.commit_group;" ::: "memory")
#define CP_WAIT3()  asm volatile("cp.async.wait_group 3;" ::: "memory")

__device__ __forceinline__ void mma_f16(float* c, const unsigned* a,
                                        unsigned b0, unsigned b1) {
    asm volatile(
        "mma.sync.aligned.m16n8k16.row.col.f32.f16.f16.f32 "
        "{%0,%1,%2,%3}, {%4,%5,%6,%7}, {%8,%9}, {%0,%1,%2,%3};"
        : "+f"(c[0]), "+f"(c[1]), "+f"(c[2]), "+f"(c[3])
        : "r"(a[0]), "r"(a[1]), "r"(a[2]), "r"(a[3]), "r"(b0), "r"(b1));
}
__device__ __forceinline__ void ldsm_x4(unsigned* r, uint32_t addr) {
    asm volatile("ldmatrix.sync.aligned.m8n8.x4.shared.b16 {%0,%1,%2,%3}, [%4];"
                 : "=r"(r[0]), "=r"(r[1]), "=r"(r[2]), "=r"(r[3]) : "r"(addr));
}
__device__ __forceinline__ unsigned h2u(__half2 h) {
    return *reinterpret_cast<unsigned*>(&h);
}

// ---------------- prep (split) ----------------
#define N_CVTX (MROWS * KDIM / 4)
#define N_CVTW (QKV_N * KDIM / 4)
#define N_CVTP (DIM * KDIM / 4)
#define N_BIAS QKV_N
#define N_CPB  (TBL * NH)
#define N_WTOT (N_CVTW + N_CVTP + N_BIAS + N_CPB)

__global__ void conv_x(const float* __restrict__ x) {
    long long i = (long long)blockIdx.x * blockDim.x + threadIdx.x;
    long long stride = (long long)gridDim.x * blockDim.x;
    for (; i < N_CVTX; i += stride) {
        float4 v = ((const float4*)x)[i];
        ((__half2*)g_xh)[2 * i]     = __floats2half2_rn(v.x, v.y);
        ((__half2*)g_xh)[2 * i + 1] = __floats2half2_rn(v.z, v.w);
    }
}

__global__ void conv_w(const float* __restrict__ qkv_w,
                       const float* __restrict__ proj_w,
                       const float* __restrict__ q_bias,
                       const float* __restrict__ v_bias,
                       const float* __restrict__ table,
                       const float* __restrict__ w1,
                       const float* __restrict__ b1,
                       const float* __restrict__ w2) {
    long long id = (long long)blockIdx.x * blockDim.x + threadIdx.x;
    if (id < N_CVTW) {
        float4 v = ((const float4*)qkv_w)[id];
        ((__half2*)g_wh)[2 * id]     = __floats2half2_rn(v.x, v.y);
        ((__half2*)g_wh)[2 * id + 1] = __floats2half2_rn(v.z, v.w);
        return;
    }
    id -= N_CVTW;
    if (id < N_CVTP) {
        float4 v = ((const float4*)proj_w)[id];
        ((__half2*)g_pwh)[2 * id]     = __floats2half2_rn(v.x, v.y);
        ((__half2*)g_pwh)[2 * id + 1] = __floats2half2_rn(v.z, v.w);
        return;
    }
    id -= N_CVTP;
    if (id < N_BIAS) {
        int n = (int)id;
        float b;
        if (n < DIM)          b = q_bias[n];
        else if (n < 2 * DIM) b = 0.0f;
        else                  b = v_bias[n - 2 * DIM];
        g_qkv_bias[n] = b;
        return;
    }
    id -= N_BIAS;
    if (id < N_CPB) {
        int t = (int)id / NH;
        int h = (int)id % NH;
        float c0 = table[t * 2 + 0];
        float c1 = table[t * 2 + 1];
        const float* w2h = w2 + h * CPBH;
        float acc = 0.0f;
        for (int j = 0; j < CPBH; j++) {
            float hid = fmaxf(c0 * w1[j * 2 + 0] + c1 * w1[j * 2 + 1] + b1[j], 0.0f);
            acc += hid * w2h[j];
        }
        g_bias_table[t * NH + h] = 16.0f / (1.0f + expf(-acc));
    }
}

// ---------------- bmF build ----------------
#define BMF_THREADS (NWMASK * NH * 4 * 7 * 32)

__global__ void bmf_build(const float* __restrict__ mask,
                          const int* __restrict__ rel_idx) {
    int e = blockIdx.x * 256 + threadIdx.x;
    if (e >= BMF_THREADS) return;
    int lane = e & 31;
    int rest = e >> 5;
    int t  = rest % 7;  rest /= 7;
    int mi = rest & 3;  rest >>= 2;
    int h  = rest % NH;
    int w  = rest / NH;
    int r  = lane >> 2, cc = lane & 3;
    int i0 = mi * 16 + r, i1 = i0 + 8;
    int j0 = t * 8 + 2 * cc, j1 = j0 + 1;
    const float* mw = mask + (size_t)w * NN;
    float4 o;
    o.x = (i0 < NTOK && j0 < NTOK) ? g_bias_table[rel_idx[i0 * NTOK + j0] * NH + h] + mw[i0 * NTOK + j0] : -1e30f;
    o.y = (i0 < NTOK && j1 < NTOK) ? g_bias_table[rel_idx[i0 * NTOK + j1] * NH + h] + mw[i0 * NTOK + j1] : -1e30f;
    o.z = (i1 < NTOK && j0 < NTOK) ? g_bias_table[rel_idx[i1 * NTOK + j0] * NH + h] + mw[i1 * NTOK + j0] : -1e30f;
    o.w = (i1 < NTOK && j1 < NTOK) ? g_bias_table[rel_idx[i1 * NTOK + j1] * NH + h] + mw[i1 * NTOK + j1] : -1e30f;
    *(float4*)(g_bmF + (size_t)e * 4) = o;
}

// ---------------- fp16 GEMM: 256x128, 64x64 warps, 5-stage cp.async --------
#define LDH     40
#define A_ST    (256 * LDH)      // 10240 halfs
#define B_ST    (128 * LDH)      // 5120 halfs
#define STAGE_H (A_ST + B_ST)    // 15360 halfs = 30720 B
#define NSTG    5
#define GSMEM   (NSTG * STAGE_H * 2)   // 153600 B

__global__ void __launch_bounds__(256, 1)
gemm_h4(const __half* __restrict__ A, const __half* __restrict__ W,
        const float* __restrict__ bias, float* __restrict__ C, int Ntot) {
    extern __shared__ __half smh[];
    const uint32_t sbase = smem_u32(smh);
    const int tid  = threadIdx.x;
    const int lane = tid & 31;
    const int wid  = tid >> 5;
    const int warpM = (wid >> 1) * 64;
    const int warpN = (wid & 1) * 64;
    const int bm = blockIdx.y * 256;
    const int bn = blockIdx.x * 128;

    const int sr = tid >> 2;
    const int un = tid & 3;
    const __half* Ag = A + (size_t)(bm + sr) * KDIM + un * 8;
    const __half* Wg = W + (size_t)(bn + sr) * KDIM + un * 8;
    const uint32_t stgOff = (uint32_t)(sr * LDH + un * 8) * 2;

    float c[4][8][4];
#pragma unroll
    for (int mi = 0; mi < 4; mi++)
#pragma unroll
        for (int ni = 0; ni < 8; ni++)
#pragma unroll
            for (int e = 0; e < 4; e++) c[mi][ni][e] = 0.0f;

    const int aRow = (lane & 7) + ((lane >> 3) & 1) * 8;
    const int aCol = ((lane >> 4) & 1) * 8;
    const int bRow = (lane & 7) + ((lane >> 4) & 1) * 8;
    const int bCol = ((lane >> 3) & 1) * 8;
    const uint32_t aFrag = sbase + (uint32_t)((warpM + aRow) * LDH + aCol) * 2;
    const uint32_t bFrag = sbase + (uint32_t)(A_ST + (warpN + bRow) * LDH + bCol) * 2;

#define ISSUE(stg, ch) do { \
    uint32_t _b = sbase + (stg) * (STAGE_H * 2) + stgOff; \
    const __half* _a = Ag + (ch) * 32; \
    cp16(_b,                  _a); \
    cp16(_b + 64 * LDH * 2,   _a + (size_t)64 * KDIM); \
    cp16(_b + 128 * LDH * 2,  _a + (size_t)128 * KDIM); \
    cp16(_b + 192 * LDH * 2,  _a + (size_t)192 * KDIM); \
    const __half* _w = Wg + (ch) * 32; \
    uint32_t _bb = _b + A_ST * 2; \
    cp16(_bb,                 _w); \
    cp16(_bb + 64 * LDH * 2,  _w + (size_t)64 * KDIM); \
} while (0)

    // prologue: fill 4 of 5 stages
    ISSUE(0, 0); CP_COMMIT();
    ISSUE(1, 1); CP_COMMIT();
    ISSUE(2, 2); CP_COMMIT();
    ISSUE(3, 3); CP_COMMIT();

#pragma unroll
    for (int ch = 0; ch < 12; ch++) {
        const int stg = ch % NSTG;
        CP_WAIT3();            // oldest outstanding group (chunk ch) complete
        __syncthreads();       // all warps done reading stage being overwritten
        if (ch + 4 < 12) { ISSUE((ch + 4) % NSTG, ch + 4); }
        CP_COMMIT();

        const uint32_t aB = aFrag + stg * (STAGE_H * 2);
        const uint32_t bB = bFrag + stg * (STAGE_H * 2);
#pragma unroll
        for (int s2 = 0; s2 < 2; s2++) {
            unsigned af[4][4], bf[4][4];
#pragma unroll
            for (int mi = 0; mi < 4; mi++)
                ldsm_x4(af[mi], aB + mi * (16 * LDH * 2) + s2 * 32);
#pragma unroll
            for (int p = 0; p < 4; p++)
                ldsm_x4(bf[p], bB + p * (16 * LDH * 2) + s2 * 32);
#pragma unroll
            for (int mi = 0; mi < 4; mi++)
#pragma unroll
                for (int p = 0; p < 4; p++) {
                    mma_f16(c[mi][2 * p],     af[mi], bf[p][0], bf[p][1]);
                    mma_f16(c[mi][2 * p + 1], af[mi], bf[p][2], bf[p][3]);
                }
        }
    }
#undef ISSUE

    const int r  = lane >> 2;
    const int cc = lane & 3;
#pragma unroll
    for (int mi = 0; mi < 4; mi++) {
        int row0 = bm + warpM + mi * 16 + r;
#pragma unroll
        for (int ni = 0; ni < 8; ni++) {
            int col = bn + warpN + ni * 8 + cc * 2;
            float2 b2 = *(const float2*)(bias + col);
            *(float2*)(C + (size_t)row0 * Ntot + col) =
                make_float2(c[mi][ni][0] + b2.x, c[mi][ni][1] + b2.y);
            *(float2*)(C + (size_t)(row0 + 8) * Ntot + col) =
                make_float2(c[mi][ni][2] + b2.x, c[mi][ni][3] + b2.y);
        }
    }
}

// ---------------- tensor-core attention (R10 attn7, verbatim) ----------
#define QK_LD 40
#define VT_LD 72

__global__ void __launch_bounds__(128)
attn7(const float* __restrict__ logit_scale) {
    const int bh = blockIdx.x;
    const int b = bh / NH;
    const int h = bh - b * NH;
    const int tid  = threadIdx.x;
    const int lane = tid & 31;
    const int mi   = tid >> 5;

    __shared__ __align__(16) __half qh[64 * QK_LD];
    __shared__ __align__(16) __half qr[64 * QK_LD];
    __shared__ __align__(16) __half kh[64 * QK_LD];
    __shared__ __align__(16) __half kr[64 * QK_LD];
    __shared__ __align__(16) __half vh[HD * VT_LD];
    __shared__ __align__(16) __half vr[HD * VT_LD];

    for (int e = tid; e < (64 - NTOK) * QK_LD / 2; e += 128) {
        ((unsigned*)(qh + NTOK * QK_LD))[e] = 0;
        ((unsigned*)(qr + NTOK * QK_LD))[e] = 0;
        ((unsigned*)(kh + NTOK * QK_LD))[e] = 0;
        ((unsigned*)(kr + NTOK * QK_LD))[e] = 0;
    }
    for (int e = tid; e < HD * 12; e += 128) {
        int rowd = e / 12, cu = e % 12;
        ((unsigned*)(vh + rowd * VT_LD + 48))[cu] = 0;
        ((unsigned*)(vr + rowd * VT_LD + 48))[cu] = 0;
    }

    const float scale = __expf(fminf(__ldg(logit_scale + h), 4.605170185988091f));
    const float* base = g_qkv + (size_t)b * NTOK * QKV_N + h * HD;

    for (int t = tid; t < 2 * NTOK; t += 128) {
        int isK = t >= NTOK;
        int row = isK ? t - NTOK : t;
        const float* src = base + (size_t)row * QKV_N + (isK ? DIM : 0);
        float4 xs[8];
#pragma unroll
        for (int p = 0; p < 8; p++) xs[p] = *(const float4*)(src + p * 4);
        float sq = 0.0f;
#pragma unroll
        for (int p = 0; p < 8; p++)
            sq += xs[p].x * xs[p].x + xs[p].y * xs[p].y + xs[p].z * xs[p].z + xs[p].w * xs[p].w;
        float fs = (isK ? 1.0f : scale) / fmaxf(sqrtf(sq), 1e-12f);
        __half2* dh = (__half2*)((isK ? kh : qh) + row * QK_LD);
        __half2* dr = (__half2*)((isK ? kr : qr) + row * QK_LD);
#pragma unroll
        for (int p = 0; p < 8; p++) {
            float f0 = xs[p].x * fs, f1 = xs[p].y * fs;
            float f2 = xs[p].z * fs, f3 = xs[p].w * fs;
            __half2 h0 = __floats2half2_rn(f0, f1);
            __half2 h1 = __floats2half2_rn(f2, f3);
            float2 b0 = __half22float2(h0);
            float2 b1 = __half22float2(h1);
            dh[2 * p]     = h0;
            dh[2 * p + 1] = h1;
            dr[2 * p]     = __floats2half2_rn(f0 - b0.x, f1 - b0.y);
            dr[2 * p + 1] = __floats2half2_rn(f2 - b1.x, f3 - b1.y);
        }
    }
    {
        const float* vsrc = base + 2 * DIM;
        for (int e = tid; e < NTOK * 8; e += 128) {
            int row = e >> 3, d4 = (e & 7) * 4;
            float4 v = *(const float4*)(vsrc + (size_t)row * QKV_N + d4);
            float vals[4] = {v.x, v.y, v.z, v.w};
#pragma unroll
            for (int cdx = 0; cdx < 4; cdx++) {
                int d = d4 + cdx;
                __half hv = __float2half_rn(vals[cdx]);
                vh[d * VT_LD + row] = hv;
                vr[d * VT_LD + row] = __float2half_rn(vals[cdx] - __half2float(hv));
            }
        }
    }
    __syncthreads();

    const int aRow = (lane & 7) + ((lane >> 3) & 1) * 8;
    const int aCol = ((lane >> 4) & 1) * 8;
    const int bRow = (lane & 7) + ((lane >> 4) & 1) * 8;
    const int bCol = ((lane >> 3) & 1) * 8;
    const uint32_t qhB = smem_u32(qh) + (uint32_t)(aRow * QK_LD + aCol) * 2;
    const uint32_t qrB = smem_u32(qr) + (uint32_t)(aRow * QK_LD + aCol) * 2;
    const uint32_t khB = smem_u32(kh) + (uint32_t)(bRow * QK_LD + bCol) * 2;
    const uint32_t krB = smem_u32(kr) + (uint32_t)(bRow * QK_LD + bCol) * 2;
    const uint32_t vhB = smem_u32(vh) + (uint32_t)(bRow * VT_LD + bCol) * 2;
    const uint32_t vrB = smem_u32(vr) + (uint32_t)(bRow * VT_LD + bCol) * 2;

    const int r  = lane >> 2;
    const int cc = lane & 3;
    const float* bmbase = g_bmF + ((size_t)(b & (NWMASK - 1)) * NH + h) * BMF_PER_WH;

    float4 bm[7];
    {
        const float4* bmp = (const float4*)(bmbase + (size_t)mi * 7 * 128) + lane;
#pragma unroll
        for (int t = 0; t < 7; t++) bm[t] = bmp[t * 32];
    }
    unsigned qfh[2][4], qfr[2][4];
#pragma unroll
    for (int kc = 0; kc < 2; kc++) {
        ldsm_x4(qfh[kc], qhB + (uint32_t)(mi * 16 * QK_LD + kc * 16) * 2);
        ldsm_x4(qfr[kc], qrB + (uint32_t)(mi * 16 * QK_LD + kc * 16) * 2);
    }
    float c[7][4];
#pragma unroll
    for (int t = 0; t < 7; t++)
#pragma unroll
        for (int e = 0; e < 4; e++) c[t][e] = 0.0f;
#pragma unroll
    for (int tp = 0; tp < 4; tp++) {
#pragma unroll
        for (int kc = 0; kc < 2; kc++) {
            unsigned kk[4], rrf[4];
            ldsm_x4(kk,  khB + (uint32_t)(tp * 16 * QK_LD + kc * 16) * 2);
            ldsm_x4(rrf, krB + (uint32_t)(tp * 16 * QK_LD + kc * 16) * 2);
            mma_f16(c[2 * tp], qfh[kc], kk[0], kk[1]);
            mma_f16(c[2 * tp], qfr[kc], kk[0], kk[1]);
            mma_f16(c[2 * tp], qfh[kc], rrf[0], rrf[1]);
            if (2 * tp + 1 < 7) {
                mma_f16(c[2 * tp + 1], qfh[kc], kk[2], kk[3]);
                mma_f16(c[2 * tp + 1], qfr[kc], kk[2], kk[3]);
                mma_f16(c[2 * tp + 1], qfh[kc], rrf[2], rrf[3]);
            }
        }
    }
#pragma unroll
    for (int t = 0; t < 7; t++) {
        c[t][0] += bm[t].x; c[t][1] += bm[t].y;
        c[t][2] += bm[t].z; c[t][3] += bm[t].w;
    }
    float mx0 = -1e30f, mx1 = -1e30f;
#pragma unroll
    for (int t = 0; t < 7; t++) {
        mx0 = fmaxf(mx0, fmaxf(c[t][0], c[t][1]));
        mx1 = fmaxf(mx1, fmaxf(c[t][2], c[t][3]));
    }
    mx0 = fmaxf(mx0, __shfl_xor_sync(0xffffffffu, mx0, 1));
    mx0 = fmaxf(mx0, __shfl_xor_sync(0xffffffffu, mx0, 2));
    mx1 = fmaxf(mx1, __shfl_xor_sync(0xffffffffu, mx1, 1));
    mx1 = fmaxf(mx1, __shfl_xor_sync(0xffffffffu, mx1, 2));

    unsigned ph[7], phb[7], pr[7], prb[7];
    float s0 = 0.0f, s1 = 0.0f;
#pragma unroll
    for (int t = 0; t < 7; t++) {
        float p0 = __expf(c[t][0] - mx0);
        float p1 = __expf(c[t][1] - mx0);
        float p2 = __expf(c[t][2] - mx1);
        float p3 = __expf(c[t][3] - mx1);
        s0 += p0 + p1; s1 += p2 + p3;
        __half2 h0 = __floats2half2_rn(p0, p1);
        __half2 h1 = __floats2half2_rn(p2, p3);
        float2 f0 = __half22float2(h0);
        float2 f1 = __half22float2(h1);
        ph[t]  = h2u(h0);
        phb[t] = h2u(h1);
        pr[t]  = h2u(__floats2half2_rn(p0 - f0.x, p1 - f0.y));
        prb[t] = h2u(__floats2half2_rn(p2 - f1.x, p3 - f1.y));
    }
    s0 += __shfl_xor_sync(0xffffffffu, s0, 1);
    s0 += __shfl_xor_sync(0xffffffffu, s0, 2);
    s1 += __shfl_xor_sync(0xffffffffu, s1, 1);
    s1 += __shfl_xor_sync(0xffffffffu, s1, 2);

    float o[4][4];
#pragma unroll
    for (int nt = 0; nt < 4; nt++)
#pragma unroll
        for (int e = 0; e < 4; e++) o[nt][e] = 0.0f;
#pragma unroll
    for (int s = 0; s < 4; s++) {
        unsigned ah[4] = { ph[2 * s], phb[2 * s],
                           (s < 3) ? ph[2 * s + 1] : 0u,
                           (s < 3) ? phb[2 * s + 1] : 0u };
        unsigned ar[4] = { pr[2 * s], prb[2 * s],
                           (s < 3) ? pr[2 * s + 1] : 0u,
                           (s < 3) ? prb[2 * s + 1] : 0u };
#pragma unroll
        for (int dp = 0; dp < 2; dp++) {
            unsigned vv[4], vw[4];
            ldsm_x4(vv, vhB + (uint32_t)(dp * 16 * VT_LD + s * 16) * 2);
            ldsm_x4(vw, vrB + (uint32_t)(dp * 16 * VT_LD + s * 16) * 2);
            mma_f16(o[2 * dp],     ah, vv[0], vv[1]);
            mma_f16(o[2 * dp],     ar, vv[0], vv[1]);
            mma_f16(o[2 * dp],     ah, vw[0], vw[1]);
            mma_f16(o[2 * dp + 1], ah, vv[2], vv[3]);
            mma_f16(o[2 * dp + 1], ar, vv[2], vv[3]);
            mma_f16(o[2 * dp + 1], ah, vw[2], vw[3]);
        }
    }
    float inv0 = 1.0f / s0;
    float inv1 = 1.0f / s1;
    int i0 = mi * 16 + r;
    if (i0 < NTOK) {
        __half* dst = g_atth + ((size_t)b * NTOK + i0) * DIM + h * HD + 2 * cc;
#pragma unroll
        for (int nt = 0; nt < 4; nt++)
            *(__half2*)(dst + nt * 8) = __floats2half2_rn(o[nt][0] * inv0, o[nt][1] * inv0);
    }
    int i1 = i0 + 8;
    if (i1 < NTOK) {
        __half* dst = g_atth + ((size_t)b * NTOK + i1) * DIM + h * HD + 2 * cc;
#pragma unroll
        for (int nt = 0; nt < 4; nt++)
            *(__half2*)(dst + nt * 8) = __floats2half2_rn(o[nt][2] * inv1, o[nt][3] * inv1);
    }
}

// ---------------- launch ----------------
extern "C" void kernel_launch(void* const* d_in, const int* in_sizes, int n_in,
                              void* d_out, int out_size) {
    const float* x           = (const float*)d_in[0];
    const float* mask        = (const float*)d_in[1];
    const float* qkv_w       = (const float*)d_in[2];
    const float* q_bias      = (const float*)d_in[3];
    const float* v_bias      = (const float*)d_in[4];
    const float* logit_scale = (const float*)d_in[5];
    const float* cpb_w1      = (const float*)d_in[6];
    const float* cpb_b1      = (const float*)d_in[7];
    const float* cpb_w2      = (const float*)d_in[8];
    const float* proj_w      = (const float*)d_in[9];
    const float* proj_b      = (const float*)d_in[10];
    const float* rel_table   = (const float*)d_in[11];
    const int*   rel_idx     = (const int*)d_in[12];
    float* out = (float*)d_out;

    float*  qkv_scratch;  cudaGetSymbolAddress((void**)&qkv_scratch, g_qkv);
    __half* xh;           cudaGetSymbolAddress((void**)&xh, g_xh);
    __half* atth;         cudaGetSymbolAddress((void**)&atth, g_atth);
    __half* wh;           cudaGetSymbolAddress((void**)&wh, g_wh);
    __half* pwh;          cudaGetSymbolAddress((void**)&pwh, g_pwh);
    float*  qkv_bias_ptr; cudaGetSymbolAddress((void**)&qkv_bias_ptr, g_qkv_bias);

    cudaFuncSetAttribute(gemm_h4, cudaFuncAttributeMaxDynamicSharedMemorySize, GSMEM);

    // launch 0: x -> half
    conv_x<<<1184, 256>>>(x);
    // launch 1: weights -> half + qkv bias + CPB MLP
    conv_w<<<(N_WTOT + 255) / 256, 256>>>(qkv_w, proj_w, q_bias, v_bias,
                                          rel_table, cpb_w1, cpb_b1, cpb_w2);
    // launch 2: fragment-layout bias+mask
    bmf_build<<<(BMF_THREADS + 255) / 256, 256>>>(mask, rel_idx);

    // launch 3 (ncu profile slot): QKV GEMM (5-stage pipeline)
    {
        dim3 grid(QKV_N / 128, MROWS / 256);
        gemm_h4<<<grid, 256, GSMEM>>>(xh, wh, qkv_bias_ptr, qkv_scratch, QKV_N);
    }

    // launch 4: attention (R10 design, verbatim)
    attn7<<<B_WIN * NH, 128>>>(logit_scale);

    // launch 5: proj GEMM
    {
        dim3 grid(DIM / 128, MROWS / 256);
        gemm_h4<<<grid, 256, GSMEM>>>(atth, pwh, proj_b, out, DIM);
    }
}

// round 14
// speedup vs baseline: 1.5622x; 1.5622x over previous
#include <cuda_runtime.h>
#include <cuda_fp16.h>
#include <math.h>
#include <stdint.h>

// ---------------- problem constants ----------------
#define B_WIN   2048
#define NTOK    49
#define DIM     384
#define NH      12
#define HD      32
#define NWMASK  64
#define TBL     169
#define CPBH    512
#define QKV_N   1152
#define MROWS   (B_WIN * NTOK)    // 100352
#define NN      (NTOK * NTOK)     // 2401
#define KDIM    384

// ---------------- scratch (device globals) ----------------
__device__ float  g_qkv[(size_t)MROWS * QKV_N];
__device__ __half g_xh[(size_t)MROWS * KDIM];
__device__ __half g_atth[(size_t)MROWS * DIM];
__device__ __half g_wh[(size_t)QKV_N * KDIM];
__device__ __half g_pwh[(size_t)DIM * KDIM];
__device__ float  g_bias_table[TBL * NH];
__device__ float  g_qkv_bias[QKV_N];
// bias+mask in mma C-fragment layout: [w][h][mi(4)][t(7)][lane(32)][4]
#define BMF_PER_WH (4 * 7 * 128)
__device__ float  g_bmF[(size_t)NWMASK * NH * BMF_PER_WH];

// ---------------- helpers ----------------
__device__ __forceinline__ uint32_t smem_u32(const void* p) {
    uint32_t a;
    asm("{ .reg .u64 t; cvta.to.shared.u64 t, %1; cvt.u32.u64 %0, t; }" : "=r"(a) : "l"(p));
    return a;
}
__device__ __forceinline__ void cp16(uint32_t dst, const void* src) {
    asm volatile("cp.async.ca.shared.global [%0], [%1], 16;" :: "r"(dst), "l"(src));
}
#define CP_COMMIT() asm volatile("cp.async.commit_group;" ::: "memory")
#define CP_WAIT1()  asm volatile("cp.async.wait_group 1;" ::: "memory")

__device__ __forceinline__ void mma_f16(float* c, const unsigned* a,
                                        unsigned b0, unsigned b1) {
    asm volatile(
        "mma.sync.aligned.m16n8k16.row.col.f32.f16.f16.f32 "
        "{%0,%1,%2,%3}, {%4,%5,%6,%7}, {%8,%9}, {%0,%1,%2,%3};"
        : "+f"(c[0]), "+f"(c[1]), "+f"(c[2]), "+f"(c[3])
        : "r"(a[0]), "r"(a[1]), "r"(a[2]), "r"(a[3]), "r"(b0), "r"(b1));
}
__device__ __forceinline__ void ldsm_x4(unsigned* r, uint32_t addr) {
    asm volatile("ldmatrix.sync.aligned.m8n8.x4.shared.b16 {%0,%1,%2,%3}, [%4];"
                 : "=r"(r[0]), "=r"(r[1]), "=r"(r[2]), "=r"(r[3]) : "r"(addr));
}
__device__ __forceinline__ unsigned h2u(__half2 h) {
    return *reinterpret_cast<unsigned*>(&h);
}

// ---------------- fused prep ----------------
#define N_CVTX (MROWS * KDIM / 4)
#define N_CVTW (QKV_N * KDIM / 4)
#define N_CVTP (DIM * KDIM / 4)
#define N_BIAS QKV_N
#define N_CPB  (TBL * NH)
#define N_TOT  (N_CVTX + N_CVTW + N_CVTP + N_BIAS + N_CPB)

__global__ void prep_fused(const float* __restrict__ x,
                           const float* __restrict__ qkv_w,
                           const float* __restrict__ proj_w,
                           const float* __restrict__ q_bias,
                           const float* __restrict__ v_bias,
                           const float* __restrict__ table,
                           const float* __restrict__ w1,
                           const float* __restrict__ b1,
                           const float* __restrict__ w2) {
    long long id = (long long)blockIdx.x * blockDim.x + threadIdx.x;
    if (id < N_CVTX) {
        float4 v = ((const float4*)x)[id];
        ((__half2*)g_xh)[2 * id]     = __floats2half2_rn(v.x, v.y);
        ((__half2*)g_xh)[2 * id + 1] = __floats2half2_rn(v.z, v.w);
        return;
    }
    id -= N_CVTX;
    if (id < N_CVTW) {
        float4 v = ((const float4*)qkv_w)[id];
        ((__half2*)g_wh)[2 * id]     = __floats2half2_rn(v.x, v.y);
        ((__half2*)g_wh)[2 * id + 1] = __floats2half2_rn(v.z, v.w);
        return;
    }
    id -= N_CVTW;
    if (id < N_CVTP) {
        float4 v = ((const float4*)proj_w)[id];
        ((__half2*)g_pwh)[2 * id]     = __floats2half2_rn(v.x, v.y);
        ((__half2*)g_pwh)[2 * id + 1] = __floats2half2_rn(v.z, v.w);
        return;
    }
    id -= N_CVTP;
    if (id < N_BIAS) {
        int n = (int)id;
        float b;
        if (n < DIM)          b = q_bias[n];
        else if (n < 2 * DIM) b = 0.0f;
        else                  b = v_bias[n - 2 * DIM];
        g_qkv_bias[n] = b;
        return;
    }
    id -= N_BIAS;
    if (id < N_CPB) {
        int t = (int)id / NH;
        int h = (int)id % NH;
        float c0 = table[t * 2 + 0];
        float c1 = table[t * 2 + 1];
        const float* w2h = w2 + h * CPBH;
        float acc = 0.0f;
        for (int j = 0; j < CPBH; j++) {
            float hid = fmaxf(c0 * w1[j * 2 + 0] + c1 * w1[j * 2 + 1] + b1[j], 0.0f);
            acc += hid * w2h[j];
        }
        g_bias_table[t * NH + h] = 16.0f / (1.0f + expf(-acc));
    }
}

// ---------------- bmF build ----------------
#define BMF_THREADS (NWMASK * NH * 4 * 7 * 32)

__global__ void bmf_build(const float* __restrict__ mask,
                          const int* __restrict__ rel_idx) {
    int e = blockIdx.x * 256 + threadIdx.x;
    if (e >= BMF_THREADS) return;
    int lane = e & 31;
    int rest = e >> 5;
    int t  = rest % 7;  rest /= 7;
    int mi = rest & 3;  rest >>= 2;
    int h  = rest % NH;
    int w  = rest / NH;
    int r  = lane >> 2, cc = lane & 3;
    int i0 = mi * 16 + r, i1 = i0 + 8;
    int j0 = t * 8 + 2 * cc, j1 = j0 + 1;
    const float* mw = mask + (size_t)w * NN;
    float4 o;
    o.x = (i0 < NTOK && j0 < NTOK) ? g_bias_table[rel_idx[i0 * NTOK + j0] * NH + h] + mw[i0 * NTOK + j0] : -1e30f;
    o.y = (i0 < NTOK && j1 < NTOK) ? g_bias_table[rel_idx[i0 * NTOK + j1] * NH + h] + mw[i0 * NTOK + j1] : -1e30f;
    o.z = (i1 < NTOK && j0 < NTOK) ? g_bias_table[rel_idx[i1 * NTOK + j0] * NH + h] + mw[i1 * NTOK + j0] : -1e30f;
    o.w = (i1 < NTOK && j1 < NTOK) ? g_bias_table[rel_idx[i1 * NTOK + j1] * NH + h] + mw[i1 * NTOK + j1] : -1e30f;
    *(float4*)(g_bmF + (size_t)e * 4) = o;
}

// ---------------- fp16 GEMM: 256x128, 64x64 warps, 3-stage cp.async (R7) ----
#define LDH     40
#define A_ST    (256 * LDH)
#define B_ST    (128 * LDH)
#define STAGE_H (A_ST + B_ST)
#define GSMEM   (3 * STAGE_H * 2)

__global__ void __launch_bounds__(256, 1)
gemm_h2(const __half* __restrict__ A, const __half* __restrict__ W,
        const float* __restrict__ bias, float* __restrict__ C, int Ntot) {
    extern __shared__ __half smh[];
    const uint32_t sbase = smem_u32(smh);
    const int tid  = threadIdx.x;
    const int lane = tid & 31;
    const int wid  = tid >> 5;
    const int warpM = (wid >> 1) * 64;
    const int warpN = (wid & 1) * 64;
    const int bm = blockIdx.y * 256;
    const int bn = blockIdx.x * 128;

    const int sr = tid >> 2;
    const int un = tid & 3;
    const __half* Ag = A + (size_t)(bm + sr) * KDIM + un * 8;
    const __half* Wg = W + (size_t)(bn + sr) * KDIM + un * 8;
    const uint32_t stgOff = (uint32_t)(sr * LDH + un * 8) * 2;

    float c[4][8][4];
#pragma unroll
    for (int mi = 0; mi < 4; mi++)
#pragma unroll
        for (int ni = 0; ni < 8; ni++)
#pragma unroll
            for (int e = 0; e < 4; e++) c[mi][ni][e] = 0.0f;

    const int aRow = (lane & 7) + ((lane >> 3) & 1) * 8;
    const int aCol = ((lane >> 4) & 1) * 8;
    const int bRow = (lane & 7) + ((lane >> 4) & 1) * 8;
    const int bCol = ((lane >> 3) & 1) * 8;
    const uint32_t aFrag = sbase + (uint32_t)((warpM + aRow) * LDH + aCol) * 2;
    const uint32_t bFrag = sbase + (uint32_t)(A_ST + (warpN + bRow) * LDH + bCol) * 2;

#define ISSUE(stg, ch) do { \
    uint32_t _b = sbase + (stg) * (STAGE_H * 2) + stgOff; \
    const __half* _a = Ag + (ch) * 32; \
    cp16(_b,                  _a); \
    cp16(_b + 64 * LDH * 2,   _a + (size_t)64 * KDIM); \
    cp16(_b + 128 * LDH * 2,  _a + (size_t)128 * KDIM); \
    cp16(_b + 192 * LDH * 2,  _a + (size_t)192 * KDIM); \
    const __half* _w = Wg + (ch) * 32; \
    uint32_t _bb = _b + A_ST * 2; \
    cp16(_bb,                 _w); \
    cp16(_bb + 64 * LDH * 2,  _w + (size_t)64 * KDIM); \
} while (0)

    ISSUE(0, 0); CP_COMMIT();
    ISSUE(1, 1); CP_COMMIT();

#pragma unroll
    for (int ch = 0; ch < 12; ch++) {
        const int stg = ch % 3;
        CP_WAIT1();
        __syncthreads();
        if (ch + 2 < 12) { ISSUE((ch + 2) % 3, ch + 2); }
        CP_COMMIT();

        const uint32_t aB = aFrag + stg * (STAGE_H * 2);
        const uint32_t bB = bFrag + stg * (STAGE_H * 2);
#pragma unroll
        for (int s2 = 0; s2 < 2; s2++) {
            unsigned af[4][4], bf[4][4];
#pragma unroll
            for (int mi = 0; mi < 4; mi++)
                ldsm_x4(af[mi], aB + mi * (16 * LDH * 2) + s2 * 32);
#pragma unroll
            for (int p = 0; p < 4; p++)
                ldsm_x4(bf[p], bB + p * (16 * LDH * 2) + s2 * 32);
#pragma unroll
            for (int mi = 0; mi < 4; mi++)
#pragma unroll
                for (int p = 0; p < 4; p++) {
                    mma_f16(c[mi][2 * p],     af[mi], bf[p][0], bf[p][1]);
                    mma_f16(c[mi][2 * p + 1], af[mi], bf[p][2], bf[p][3]);
                }
        }
    }
#undef ISSUE

    const int r  = lane >> 2;
    const int cc = lane & 3;
#pragma unroll
    for (int mi = 0; mi < 4; mi++) {
        int row0 = bm + warpM + mi * 16 + r;
#pragma unroll
        for (int ni = 0; ni < 8; ni++) {
            int col = bn + warpN + ni * 8 + cc * 2;
            float2 b2 = *(const float2*)(bias + col);
            *(float2*)(C + (size_t)row0 * Ntot + col) =
                make_float2(c[mi][ni][0] + b2.x, c[mi][ni][1] + b2.y);
            *(float2*)(C + (size_t)(row0 + 8) * Ntot + col) =
                make_float2(c[mi][ni][2] + b2.x, c[mi][ni][3] + b2.y);
        }
    }
}

// ---------------- tensor-core attention (R10 mainloop, vectorized fills) ----
#define QK_LD 40
#define VT_LD 72

__global__ void __launch_bounds__(128)
attn9(const float* __restrict__ logit_scale) {
    const int bh = blockIdx.x;
    const int b = bh / NH;
    const int h = bh - b * NH;
    const int tid  = threadIdx.x;
    const int lane = tid & 31;
    const int mi   = tid >> 5;

    __shared__ __align__(16) __half qh[64 * QK_LD];
    __shared__ __align__(16) __half qr[64 * QK_LD];
    __shared__ __align__(16) __half kh[64 * QK_LD];
    __shared__ __align__(16) __half kr[64 * QK_LD];
    __shared__ __align__(16) __half vh[HD * VT_LD];
    __shared__ __align__(16) __half vr[HD * VT_LD];

    // zero pads (q/k rows 49..63; vT cols 48..71)
    for (int e = tid; e < (64 - NTOK) * QK_LD / 2; e += 128) {
        ((unsigned*)(qh + NTOK * QK_LD))[e] = 0;
        ((unsigned*)(qr + NTOK * QK_LD))[e] = 0;
        ((unsigned*)(kh + NTOK * QK_LD))[e] = 0;
        ((unsigned*)(kr + NTOK * QK_LD))[e] = 0;
    }
    for (int e = tid; e < HD * 12; e += 128) {
        int rowd = e / 12, cu = e % 12;
        ((unsigned*)(vh + rowd * VT_LD + 48))[cu] = 0;
        ((unsigned*)(vr + rowd * VT_LD + 48))[cu] = 0;
    }
    __syncthreads();   // zero-pad complete before fills (vT col 48/49 overlap)

    const float scale = __expf(fminf(__ldg(logit_scale + h), 4.605170185988091f));
    const float* base = g_qkv + (size_t)b * NTOK * QKV_N + h * HD;

    // q (scaled/normalized) + k (normalized), split h+r — uint4 STS.128 stores
    for (int t = tid; t < 2 * NTOK; t += 128) {
        int isK = t >= NTOK;
        int row = isK ? t - NTOK : t;
        const float* src = base + (size_t)row * QKV_N + (isK ? DIM : 0);
        float4 xs[8];
#pragma unroll
        for (int p = 0; p < 8; p++) xs[p] = *(const float4*)(src + p * 4);
        float sq = 0.0f;
#pragma unroll
        for (int p = 0; p < 8; p++)
            sq += xs[p].x * xs[p].x + xs[p].y * xs[p].y + xs[p].z * xs[p].z + xs[p].w * xs[p].w;
        float fs = (isK ? 1.0f : scale) / fmaxf(sqrtf(sq), 1e-12f);
        __half* dsth = (isK ? kh : qh) + row * QK_LD;
        __half* dstr = (isK ? kr : qr) + row * QK_LD;
#pragma unroll
        for (int g = 0; g < 4; g++) {
            float f0 = xs[2 * g].x * fs,     f1 = xs[2 * g].y * fs;
            float f2 = xs[2 * g].z * fs,     f3 = xs[2 * g].w * fs;
            float f4 = xs[2 * g + 1].x * fs, f5 = xs[2 * g + 1].y * fs;
            float f6 = xs[2 * g + 1].z * fs, f7 = xs[2 * g + 1].w * fs;
            __half2 h0 = __floats2half2_rn(f0, f1);
            __half2 h1 = __floats2half2_rn(f2, f3);
            __half2 h2 = __floats2half2_rn(f4, f5);
            __half2 h3 = __floats2half2_rn(f6, f7);
            float2 a0 = __half22float2(h0), a1 = __half22float2(h1);
            float2 a2 = __half22float2(h2), a3 = __half22float2(h3);
            uint4 uh = make_uint4(h2u(h0), h2u(h1), h2u(h2), h2u(h3));
            uint4 ur = make_uint4(
                h2u(__floats2half2_rn(f0 - a0.x, f1 - a0.y)),
                h2u(__floats2half2_rn(f2 - a1.x, f3 - a1.y)),
                h2u(__floats2half2_rn(f4 - a2.x, f5 - a2.y)),
                h2u(__floats2half2_rn(f6 - a3.x, f7 - a3.y)));
            *(uint4*)(dsth + g * 8) = uh;
            *(uint4*)(dstr + g * 8) = ur;
        }
    }
    // vT fill: row pairs -> half2 stores (adjacent tokens adjacent in vT)
    {
        const float* vsrc = base + 2 * DIM;
        for (int e = tid; e < 25 * 8; e += 128) {
            int rp = e >> 3, d4 = (e & 7) * 4;
            int r0 = 2 * rp, r1 = r0 + 1;
            float4 v0 = *(const float4*)(vsrc + (size_t)r0 * QKV_N + d4);
            float4 v1 = (r1 < NTOK)
                ? *(const float4*)(vsrc + (size_t)r1 * QKV_N + d4)
                : make_float4(0.f, 0.f, 0.f, 0.f);
            float av[4] = {v0.x, v0.y, v0.z, v0.w};
            float bv[4] = {v1.x, v1.y, v1.z, v1.w};
#pragma unroll
            for (int cdx = 0; cdx < 4; cdx++) {
                int d = d4 + cdx;
                __half2 hv = __floats2half2_rn(av[cdx], bv[cdx]);
                float2 bk = __half22float2(hv);
                *(__half2*)(vh + d * VT_LD + r0) = hv;
                *(__half2*)(vr + d * VT_LD + r0) =
                    __floats2half2_rn(av[cdx] - bk.x, bv[cdx] - bk.y);
            }
        }
    }
    __syncthreads();

    const int aRow = (lane & 7) + ((lane >> 3) & 1) * 8;
    const int aCol = ((lane >> 4) & 1) * 8;
    const int bRow = (lane & 7) + ((lane >> 4) & 1) * 8;
    const int bCol = ((lane >> 3) & 1) * 8;
    const uint32_t qhB = smem_u32(qh) + (uint32_t)(aRow * QK_LD + aCol) * 2;
    const uint32_t qrB = smem_u32(qr) + (uint32_t)(aRow * QK_LD + aCol) * 2;
    const uint32_t khB = smem_u32(kh) + (uint32_t)(bRow * QK_LD + bCol) * 2;
    const uint32_t krB = smem_u32(kr) + (uint32_t)(bRow * QK_LD + bCol) * 2;
    const uint32_t vhB = smem_u32(vh) + (uint32_t)(bRow * VT_LD + bCol) * 2;
    const uint32_t vrB = smem_u32(vr) + (uint32_t)(bRow * VT_LD + bCol) * 2;

    const int r  = lane >> 2;
    const int cc = lane & 3;
    const float* bmbase = g_bmF + ((size_t)(b & (NWMASK - 1)) * NH + h) * BMF_PER_WH;

    float4 bm[7];
    {
        const float4* bmp = (const float4*)(bmbase + (size_t)mi * 7 * 128) + lane;
#pragma unroll
        for (int t = 0; t < 7; t++) bm[t] = bmp[t * 32];
    }
    unsigned qfh[2][4], qfr[2][4];
#pragma unroll
    for (int kc = 0; kc < 2; kc++) {
        ldsm_x4(qfh[kc], qhB + (uint32_t)(mi * 16 * QK_LD + kc * 16) * 2);
        ldsm_x4(qfr[kc], qrB + (uint32_t)(mi * 16 * QK_LD + kc * 16) * 2);
    }
    float c[7][4];
#pragma unroll
    for (int t = 0; t < 7; t++)
#pragma unroll
        for (int e = 0; e < 4; e++) c[t][e] = 0.0f;
#pragma unroll
    for (int tp = 0; tp < 4; tp++) {
#pragma unroll
        for (int kc = 0; kc < 2; kc++) {
            unsigned kk[4], rrf[4];
            ldsm_x4(kk,  khB + (uint32_t)(tp * 16 * QK_LD + kc * 16) * 2);
            ldsm_x4(rrf, krB + (uint32_t)(tp * 16 * QK_LD + kc * 16) * 2);
            mma_f16(c[2 * tp], qfh[kc], kk[0], kk[1]);
            mma_f16(c[2 * tp], qfr[kc], kk[0], kk[1]);
            mma_f16(c[2 * tp], qfh[kc], rrf[0], rrf[1]);
            if (2 * tp + 1 < 7) {
                mma_f16(c[2 * tp + 1], qfh[kc], kk[2], kk[3]);
                mma_f16(c[2 * tp + 1], qfr[kc], kk[2], kk[3]);
                mma_f16(c[2 * tp + 1], qfh[kc], rrf[2], rrf[3]);
            }
        }
    }
#pragma unroll
    for (int t = 0; t < 7; t++) {
        c[t][0] += bm[t].x; c[t][1] += bm[t].y;
        c[t][2] += bm[t].z; c[t][3] += bm[t].w;
    }
    float mx0 = -1e30f, mx1 = -1e30f;
#pragma unroll
    for (int t = 0; t < 7; t++) {
        mx0 = fmaxf(mx0, fmaxf(c[t][0], c[t][1]));
        mx1 = fmaxf(mx1, fmaxf(c[t][2], c[t][3]));
    }
    mx0 = fmaxf(mx0, __shfl_xor_sync(0xffffffffu, mx0, 1));
    mx0 = fmaxf(mx0, __shfl_xor_sync(0xffffffffu, mx0, 2));
    mx1 = fmaxf(mx1, __shfl_xor_sync(0xffffffffu, mx1, 1));
    mx1 = fmaxf(mx1, __shfl_xor_sync(0xffffffffu, mx1, 2));

    unsigned ph[7], phb[7], pr[7], prb[7];
    float s0 = 0.0f, s1 = 0.0f;
#pragma unroll
    for (int t = 0; t < 7; t++) {
        float p0 = __expf(c[t][0] - mx0);
        float p1 = __expf(c[t][1] - mx0);
        float p2 = __expf(c[t][2] - mx1);
        float p3 = __expf(c[t][3] - mx1);
        s0 += p0 + p1; s1 += p2 + p3;
        __half2 h0 = __floats2half2_rn(p0, p1);
        __half2 h1 = __floats2half2_rn(p2, p3);
        float2 f0 = __half22float2(h0);
        float2 f1 = __half22float2(h1);
        ph[t]  = h2u(h0);
        phb[t] = h2u(h1);
        pr[t]  = h2u(__floats2half2_rn(p0 - f0.x, p1 - f0.y));
        prb[t] = h2u(__floats2half2_rn(p2 - f1.x, p3 - f1.y));
    }
    s0 += __shfl_xor_sync(0xffffffffu, s0, 1);
    s0 += __shfl_xor_sync(0xffffffffu, s0, 2);
    s1 += __shfl_xor_sync(0xffffffffu, s1, 1);
    s1 += __shfl_xor_sync(0xffffffffu, s1, 2);

    float o[4][4];
#pragma unroll
    for (int nt = 0; nt < 4; nt++)
#pragma unroll
        for (int e = 0; e < 4; e++) o[nt][e] = 0.0f;
#pragma unroll
    for (int s = 0; s < 4; s++) {
        unsigned ah[4] = { ph[2 * s], phb[2 * s],
                           (s < 3) ? ph[2 * s + 1] : 0u,
                           (s < 3) ? phb[2 * s + 1] : 0u };
        unsigned ar[4] = { pr[2 * s], prb[2 * s],
                           (s < 3) ? pr[2 * s + 1] : 0u,
                           (s < 3) ? prb[2 * s + 1] : 0u };
#pragma unroll
        for (int dp = 0; dp < 2; dp++) {
            unsigned vv[4], vw[4];
            ldsm_x4(vv, vhB + (uint32_t)(dp * 16 * VT_LD + s * 16) * 2);
            ldsm_x4(vw, vrB + (uint32_t)(dp * 16 * VT_LD + s * 16) * 2);
            mma_f16(o[2 * dp],     ah, vv[0], vv[1]);
            mma_f16(o[2 * dp],     ar, vv[0], vv[1]);
            mma_f16(o[2 * dp],     ah, vw[0], vw[1]);
            mma_f16(o[2 * dp + 1], ah, vv[2], vv[3]);
            mma_f16(o[2 * dp + 1], ar, vv[2], vv[3]);
            mma_f16(o[2 * dp + 1], ah, vw[2], vw[3]);
        }
    }
    float inv0 = 1.0f / s0;
    float inv1 = 1.0f / s1;
    int i0 = mi * 16 + r;
    if (i0 < NTOK) {
        __half* dst = g_atth + ((size_t)b * NTOK + i0) * DIM + h * HD + 2 * cc;
#pragma unroll
        for (int nt = 0; nt < 4; nt++)
            *(__half2*)(dst + nt * 8) = __floats2half2_rn(o[nt][0] * inv0, o[nt][1] * inv0);
    }
    int i1 = i0 + 8;
    if (i1 < NTOK) {
        __half* dst = g_atth + ((size_t)b * NTOK + i1) * DIM + h * HD + 2 * cc;
#pragma unroll
        for (int nt = 0; nt < 4; nt++)
            *(__half2*)(dst + nt * 8) = __floats2half2_rn(o[nt][2] * inv1, o[nt][3] * inv1);
    }
}

// ---------------- launch ----------------
extern "C" void kernel_launch(void* const* d_in, const int* in_sizes, int n_in,
                              void* d_out, int out_size) {
    const float* x           = (const float*)d_in[0];
    const float* mask        = (const float*)d_in[1];
    const float* qkv_w       = (const float*)d_in[2];
    const float* q_bias      = (const float*)d_in[3];
    const float* v_bias      = (const float*)d_in[4];
    const float* logit_scale = (const float*)d_in[5];
    const float* cpb_w1      = (const float*)d_in[6];
    const float* cpb_b1      = (const float*)d_in[7];
    const float* cpb_w2      = (const float*)d_in[8];
    const float* proj_w      = (const float*)d_in[9];
    const float* proj_b      = (const float*)d_in[10];
    const float* rel_table   = (const float*)d_in[11];
    const int*   rel_idx     = (const int*)d_in[12];
    float* out = (float*)d_out;

    float*  qkv_scratch;  cudaGetSymbolAddress((void**)&qkv_scratch, g_qkv);
    __half* xh;           cudaGetSymbolAddress((void**)&xh, g_xh);
    __half* atth;         cudaGetSymbolAddress((void**)&atth, g_atth);
    __half* wh;           cudaGetSymbolAddress((void**)&wh, g_wh);
    __half* pwh;          cudaGetSymbolAddress((void**)&pwh, g_pwh);
    float*  qkv_bias_ptr; cudaGetSymbolAddress((void**)&qkv_bias_ptr, g_qkv_bias);

    cudaFuncSetAttribute(gemm_h2, cudaFuncAttributeMaxDynamicSharedMemorySize, GSMEM);

    // launch 0: fused prep
    prep_fused<<<(N_TOT + 255) / 256, 256>>>(x, qkv_w, proj_w, q_bias, v_bias,
                                             rel_table, cpb_w1, cpb_b1, cpb_w2);
    // launch 1: fragment-layout bias+mask
    bmf_build<<<(BMF_THREADS + 255) / 256, 256>>>(mask, rel_idx);

    // launch 2: QKV GEMM
    {
        dim3 grid(QKV_N / 128, MROWS / 256);
        gemm_h2<<<grid, 256, GSMEM>>>(xh, wh, qkv_bias_ptr, qkv_scratch, QKV_N);
    }

    // launch 3 (ncu profile slot): attention
    attn9<<<B_WIN * NH, 128>>>(logit_scale);

    // launch 4: proj GEMM
    {
        dim3 grid(DIM / 128, MROWS / 256);
        gemm_h2<<<grid, 256, GSMEM>>>(atth, pwh, proj_b, out, DIM);
    }
}